// round 8
// baseline (speedup 1.0000x reference)
#include <cuda_runtime.h>
#include <cstdint>

#define BATCH 4
#define DIMC 256
#define MIDC 128
#define HH 128
#define WW 128
#define EPSV 1e-5f

typedef unsigned long long u64;

__device__ __forceinline__ u64 pack2(float lo, float hi) {
    u64 r;
    asm("mov.b64 %0, {%1, %2};" : "=l"(r) : "f"(lo), "f"(hi));
    return r;
}
__device__ __forceinline__ void unpack2(u64 v, float& lo, float& hi) {
    asm("mov.b64 {%0, %1}, %2;" : "=f"(lo), "=f"(hi) : "l"(v));
}
__device__ __forceinline__ void fma2(u64& d, u64 a, u64 b) {
    asm("fma.rn.f32x2 %0, %1, %2, %0;" : "+l"(d) : "l"(a), "l"(b));
}
__device__ __forceinline__ uint32_t smem_u32(const void* p) {
    return (uint32_t)__cvta_generic_to_shared(p);
}
__device__ __forceinline__ void cp4(uint32_t d, const void* s, bool valid) {
    int sz = valid ? 4 : 0;
    asm volatile("cp.async.ca.shared.global [%0], [%1], 4, %2;" :: "r"(d), "l"(s), "r"(sz));
}
__device__ __forceinline__ void cp16(uint32_t d, const void* s) {
    asm volatile("cp.async.cg.shared.global [%0], [%1], 16;" :: "r"(d), "l"(s));
}
__device__ __forceinline__ void cp_commit() { asm volatile("cp.async.commit_group;"); }
__device__ __forceinline__ void cp_wait0() { asm volatile("cp.async.wait_group 0;"); }

// Scratch (device globals: allocation-free)
__device__ float g_colmax[BATCH * MIDC * WW];
__device__ float g_rowmax[BATCH * MIDC * HH];
__device__ float g_r[(size_t)BATCH * DIMC * HH * WW];

__global__ void init_max_kernel() {
    int i = blockIdx.x * blockDim.x + threadIdx.x;
    if (i < BATCH * MIDC * WW) {
        g_colmax[i] = 0.f;
        g_rowmax[i] = 0.f;
    }
}

// 3x3 conv (pad=1) + BN + ReLU. Tile 8h x 64w, CO=8.
// Thread xx owns pixel pairs (xx, xx+32) -> acc[co][0], (xx+16, xx+48) -> acc[co][1].
// Interleaved tile z[i] = (raw[i], raw[i+32]): tap dx operand = z[xx+dx] (pure LDS.64).
// mode 0: col max over h ; mode 1: row max over w ; mode 2: store NCHW.
__global__ __launch_bounds__(128, 4)
void conv3_kernel(const float* __restrict__ in, const float* __restrict__ wgt,
                  const float* __restrict__ gamma, const float* __restrict__ beta,
                  const float* __restrict__ mean, const float* __restrict__ var,
                  int CIN, int COUT, int mode, float* __restrict__ out)
{
    __shared__ float sRaw[2][4][10][66];     // staged raw tile (halo, zeros at border)
    __shared__ u64 sZ[4][10][34];            // interleaved pairs
    __shared__ float sWraw[2][288];          // raw weights
    __shared__ ulonglong2 sWp[8][4][3];      // dup (dx0,dx1)
    __shared__ u64 sW2[8][4][3];             // dup dx2
    __shared__ float sSc[8], sSh[8];
    __shared__ int sMax[8][64];

    const int wt = blockIdx.x & 1, ht = blockIdx.x >> 1;
    const int w0 = wt * 64, h0 = ht * 8;
    const int co0 = blockIdx.y * 8;
    const int b = blockIdx.z;
    const int xx = threadIdx.x, yy = threadIdx.y;
    const int tid = yy * 16 + xx;

    if (tid < 8) {
        int c = co0 + tid;
        float sc = gamma[c] * rsqrtf(var[c] + EPSV);
        sSc[tid] = sc;
        sSh[tid] = beta[c] - mean[c] * sc;
    }
    for (int i = tid; i < 512; i += 128) ((int*)sMax)[i] = 0;

    const float* inb = in + (size_t)b * CIN * HH * WW;
    const int nch = CIN / 4;

    auto stage = [&](int buf, int ci0) {
        for (int idx = tid; idx < 2640; idx += 128) {
            int ci = idx / 660, r = idx % 660;
            int hh = r / 66, c = r % 66;
            int gh = h0 - 1 + hh, gw = w0 - 1 + c;
            bool valid = ((unsigned)gh < (unsigned)HH) && ((unsigned)gw < (unsigned)WW);
            cp4(smem_u32(&sRaw[buf][ci][hh][c]),
                inb + (size_t)(ci0 + ci) * HH * WW + (valid ? gh : 0) * WW + (valid ? gw : 0),
                valid);
        }
        if (tid < 72) {
            int co = tid / 9, q = tid % 9;
            cp16(smem_u32(&sWraw[buf][co * 36 + q * 4]),
                 wgt + ((size_t)(co0 + co) * CIN + ci0) * 9 + q * 4);
        }
    };

    stage(0, 0);
    cp_commit();

    u64 acc[8][2];
#pragma unroll
    for (int co = 0; co < 8; co++) { acc[co][0] = 0ULL; acc[co][1] = 0ULL; }

    for (int ch = 0; ch < nch; ch++) {
        int buf = ch & 1;
        cp_wait0();
        __syncthreads();
        if (ch + 1 < nch) { stage(buf ^ 1, (ch + 1) * 4); cp_commit(); }

        // expand weights (BN-scaled, duplicated halves)
        for (int idx = tid; idx < 288; idx += 128) {
            int co = idx / 36, r = idx % 36, ci = r / 9, k = r % 9;
            int dy = k / 3, dx = k % 3;
            float w = sWraw[buf][idx] * sSc[co];
            u64 d = pack2(w, w);
            if (dx == 2) sW2[co][ci][dy] = d;
            else ((u64*)&sWp[co][ci][dy])[dx] = d;
        }
        // build interleaved tile
        for (int idx = tid; idx < 1360; idx += 128) {
            int ci = idx / 340, r = idx % 340;
            int hh = r / 34, i = r % 34;
            const float* rr = &sRaw[buf][ci][hh][0];
            sZ[ci][hh][i] = pack2(rr[i], rr[i + 32]);
        }
        __syncthreads();

        for (int ci = 0; ci < 4; ci++) {
#pragma unroll
            for (int dy = 0; dy < 3; dy++) {
                const u64* zr = &sZ[ci][yy + dy][0];
                u64 a0 = zr[xx],      a1 = zr[xx + 1],  a2 = zr[xx + 2];
                u64 b0 = zr[xx + 16], b1 = zr[xx + 17], b2 = zr[xx + 18];
#pragma unroll
                for (int co = 0; co < 8; co++) {
                    ulonglong2 wp = sWp[co][ci][dy];
                    u64 w2v = sW2[co][ci][dy];
                    fma2(acc[co][0], wp.x, a0);
                    fma2(acc[co][1], wp.x, b0);
                    fma2(acc[co][0], wp.y, a1);
                    fma2(acc[co][1], wp.y, b1);
                    fma2(acc[co][0], w2v, a2);
                    fma2(acc[co][1], w2v, b2);
                }
            }
        }
    }

    // acc[co][0] = pixels (w0+xx, w0+xx+32) ; acc[co][1] = (w0+xx+16, w0+xx+48)
    if (mode == 2) {
#pragma unroll
        for (int co = 0; co < 8; co++) {
            float v0, v1, v2, v3;
            unpack2(acc[co][0], v0, v2);
            unpack2(acc[co][1], v1, v3);
            float* op = &out[((size_t)(b * COUT + co0 + co) * HH + h0 + yy) * WW + w0];
            op[xx]      = fmaxf(v0 + sSh[co], 0.f);
            op[xx + 16] = fmaxf(v1 + sSh[co], 0.f);
            op[xx + 32] = fmaxf(v2 + sSh[co], 0.f);
            op[xx + 48] = fmaxf(v3 + sSh[co], 0.f);
        }
    } else if (mode == 0) {
#pragma unroll
        for (int co = 0; co < 8; co++) {
            float v0, v1, v2, v3;
            unpack2(acc[co][0], v0, v2);
            unpack2(acc[co][1], v1, v3);
            atomicMax(&sMax[co][xx],      __float_as_int(fmaxf(v0 + sSh[co], 0.f)));
            atomicMax(&sMax[co][xx + 16], __float_as_int(fmaxf(v1 + sSh[co], 0.f)));
            atomicMax(&sMax[co][xx + 32], __float_as_int(fmaxf(v2 + sSh[co], 0.f)));
            atomicMax(&sMax[co][xx + 48], __float_as_int(fmaxf(v3 + sSh[co], 0.f)));
        }
        __syncthreads();
        int* gout = (int*)out;
        for (int i = tid; i < 512; i += 128) {
            int co = i >> 6, w = i & 63;
            atomicMax(&gout[(b * MIDC + co0 + co) * WW + w0 + w], sMax[co][w]);
        }
    } else {
#pragma unroll
        for (int co = 0; co < 8; co++) {
            float v0, v1, v2, v3;
            unpack2(acc[co][0], v0, v2);
            unpack2(acc[co][1], v1, v3);
            float m = fmaxf(fmaxf(v0, v1), fmaxf(v2, v3));
            atomicMax(&sMax[co][yy], __float_as_int(fmaxf(m + sSh[co], 0.f)));
        }
        __syncthreads();
        int* gout = (int*)out;
        if (tid < 64) {
            int co = tid >> 3, h = tid & 7;
            atomicMax(&gout[(b * MIDC + co0 + co) * HH + h0 + h], sMax[co][h]);
        }
    }
}

// Fused merge: r = relu( bn_p(conv3x3(s)) + bn_c1(conv1x1(x)) ),
// s[b,c,h,w] = colmax[b,c,w] + rowmax[b,c,h] (0 outside bounds).
__global__ __launch_bounds__(128, 4)
void merge_kernel(const float* __restrict__ x,
                  const float* __restrict__ pw, const float* __restrict__ pg,
                  const float* __restrict__ pb, const float* __restrict__ pm,
                  const float* __restrict__ pv,
                  const float* __restrict__ c1w, const float* __restrict__ c1g,
                  const float* __restrict__ c1b, const float* __restrict__ c1m,
                  const float* __restrict__ c1v)
{
    // overlapped region: phase A raw x tile + zA ; phase B cm/rm + zB
    __shared__ char sMem[24576 + 128];
    __shared__ float sWrawA[2][32];
    __shared__ u64 sW1[8][4];
    __shared__ float sWrawB[2][288];
    __shared__ ulonglong2 sWp[8][4][3];
    __shared__ u64 sW2[8][4][3];
    __shared__ float sScP[8], sScC[8], sSh[8];

    float (*rawA)[4][8][64] = (float (*)[4][8][64])(sMem);            // 16384 B
    u64 (*zA)[8][32]        = (u64 (*)[8][32])(sMem + 16384);         // 8192 B
    u64 (*zB)[10][34]       = (u64 (*)[10][34])(sMem);                // 10880 B
    float (*cmr)[4][66]     = (float (*)[4][66])(sMem + 10880);       // 2112 B
    float (*rmr)[4][10]     = (float (*)[4][10])(sMem + 12992);       // 320 B

    const int wt = blockIdx.x & 1, ht = blockIdx.x >> 1;
    const int w0 = wt * 64, h0 = ht * 8;
    const int co0 = blockIdx.y * 8;
    const int b = blockIdx.z;
    const int xx = threadIdx.x, yy = threadIdx.y;
    const int tid = yy * 16 + xx;

    if (tid < 8) {
        int c = co0 + tid;
        float scp = pg[c] * rsqrtf(pv[c] + EPSV);
        float scc = c1g[c] * rsqrtf(c1v[c] + EPSV);
        sScP[tid] = scp;
        sScC[tid] = scc;
        sSh[tid] = (pb[c] - pm[c] * scp) + (c1b[c] - c1m[c] * scc);
    }

    u64 acc[8][2];
#pragma unroll
    for (int co = 0; co < 8; co++) { acc[co][0] = 0ULL; acc[co][1] = 0ULL; }

    // ---- Phase A: 1x1 conv over x ----
    const float* xb = x + (size_t)b * DIMC * HH * WW;
    auto stageA = [&](int buf, int ci0) {
        for (int idx = tid; idx < 512; idx += 128) {
            int ci = idx >> 7, r = idx & 127;
            int hh = r >> 4, w4 = (r & 15) << 2;
            cp16(smem_u32(&rawA[buf][ci][hh][w4]),
                 xb + (size_t)(ci0 + ci) * HH * WW + (h0 + hh) * WW + w0 + w4);
        }
        if (tid < 8)
            cp16(smem_u32(&sWrawA[buf][tid * 4]),
                 c1w + (size_t)(co0 + tid) * DIMC + ci0);
    };

    stageA(0, 0);
    cp_commit();
    for (int ch = 0; ch < DIMC / 4; ch++) {
        int buf = ch & 1;
        cp_wait0();
        __syncthreads();
        if (ch + 1 < DIMC / 4) { stageA(buf ^ 1, (ch + 1) * 4); cp_commit(); }
        if (tid < 32) {
            int co = tid >> 2, ci = tid & 3;
            float w = sWrawA[buf][co * 4 + ci] * sScC[co];
            sW1[co][ci] = pack2(w, w);
        }
        // interleave: zA[ci][hh][i] = (row[i], row[i+32])
        for (int idx = tid; idx < 1024; idx += 128) {
            int ci = idx >> 8, r = idx & 255;
            int hh = r >> 5, i = r & 31;
            const float* rr = &rawA[buf][ci][hh][0];
            zA[ci][hh][i] = pack2(rr[i], rr[i + 32]);
        }
        __syncthreads();
        for (int ci = 0; ci < 4; ci++) {
            const u64* zr = &zA[ci][yy][0];
            u64 a = zr[xx];
            u64 bq = zr[xx + 16];
#pragma unroll
            for (int co = 0; co < 8; co++) {
                u64 wv = sW1[co][ci];
                fma2(acc[co][0], wv, a);
                fma2(acc[co][1], wv, bq);
            }
        }
    }

    // ---- Phase B: 3x3 conv over s (built on the fly, interleaved) ----
    auto stageB = [&](int buf, int ci0) {
        for (int idx = tid; idx < 264; idx += 128) {
            int ci = idx / 66, c = idx % 66;
            int gw = w0 - 1 + c;
            bool valid = (unsigned)gw < (unsigned)WW;
            cp4(smem_u32(&cmr[buf][ci][c]),
                g_colmax + (b * MIDC + ci0 + ci) * WW + (valid ? gw : 0), valid);
        }
        if (tid < 40) {
            int ci = tid / 10, hh = tid % 10;
            int gh = h0 - 1 + hh;
            bool valid = (unsigned)gh < (unsigned)HH;
            cp4(smem_u32(&rmr[buf][ci][hh]),
                g_rowmax + (b * MIDC + ci0 + ci) * HH + (valid ? gh : 0), valid);
        }
        if (tid < 72) {
            int co = tid / 9, q = tid % 9;
            cp16(smem_u32(&sWrawB[buf][co * 36 + q * 4]),
                 pw + ((size_t)(co0 + co) * MIDC + ci0) * 9 + q * 4);
        }
    };

    stageB(0, 0);
    cp_commit();
    for (int ch = 0; ch < MIDC / 4; ch++) {
        int buf = ch & 1;
        cp_wait0();
        __syncthreads();
        if (ch + 1 < MIDC / 4) { stageB(buf ^ 1, (ch + 1) * 4); cp_commit(); }

        for (int idx = tid; idx < 288; idx += 128) {
            int co = idx / 36, r = idx % 36, ci = r / 9, k = r % 9;
            int dy = k / 3, dx = k % 3;
            float w = sWrawB[buf][idx] * sScP[co];
            u64 d = pack2(w, w);
            if (dx == 2) sW2[co][ci][dy] = d;
            else ((u64*)&sWp[co][ci][dy])[dx] = d;
        }
        // build interleaved s tile: s(c) = in-bounds ? cm[c]+rm[hh] : 0
        for (int idx = tid; idx < 1360; idx += 128) {
            int ci = idx / 340, r = idx % 340;
            int hh = r / 34, i = r % 34;
            float rmv = rmr[buf][ci][hh];
            bool vh = (unsigned)(h0 + hh - 1) < (unsigned)HH;
            bool v0ok = vh && ((unsigned)(w0 + i - 1) < (unsigned)WW);
            bool v1ok = vh && ((unsigned)(w0 + i + 31) < (unsigned)WW);
            float s0 = v0ok ? (cmr[buf][ci][i] + rmv) : 0.f;
            float s1 = v1ok ? (cmr[buf][ci][i + 32] + rmv) : 0.f;
            zB[ci][hh][i] = pack2(s0, s1);
        }
        __syncthreads();

        for (int ci = 0; ci < 4; ci++) {
#pragma unroll
            for (int dy = 0; dy < 3; dy++) {
                const u64* zr = &zB[ci][yy + dy][0];
                u64 a0 = zr[xx],      a1 = zr[xx + 1],  a2 = zr[xx + 2];
                u64 b0 = zr[xx + 16], b1 = zr[xx + 17], b2 = zr[xx + 18];
#pragma unroll
                for (int co = 0; co < 8; co++) {
                    ulonglong2 wp = sWp[co][ci][dy];
                    u64 w2v = sW2[co][ci][dy];
                    fma2(acc[co][0], wp.x, a0);
                    fma2(acc[co][1], wp.x, b0);
                    fma2(acc[co][0], wp.y, a1);
                    fma2(acc[co][1], wp.y, b1);
                    fma2(acc[co][0], w2v, a2);
                    fma2(acc[co][1], w2v, b2);
                }
            }
        }
        __syncthreads();   // zB reused next chunk
    }

    // epilogue
#pragma unroll
    for (int co = 0; co < 8; co++) {
        float v0, v1, v2, v3;
        unpack2(acc[co][0], v0, v2);
        unpack2(acc[co][1], v1, v3);
        float* op = &g_r[((size_t)(b * DIMC + co0 + co) * HH + h0 + yy) * WW + w0];
        op[xx]      = fmaxf(v0 + sSh[co], 0.f);
        op[xx + 16] = fmaxf(v1 + sSh[co], 0.f);
        op[xx + 32] = fmaxf(v2 + sSh[co], 0.f);
        op[xx + 48] = fmaxf(v3 + sSh[co], 0.f);
    }
}

extern "C" void kernel_launch(void* const* d_in, const int* in_sizes, int n_in,
                              void* d_out, int out_size)
{
    const float* x    = (const float*)d_in[0];
    const float* p1w  = (const float*)d_in[1];
    const float* p1g  = (const float*)d_in[2];
    const float* p1b  = (const float*)d_in[3];
    const float* p1m  = (const float*)d_in[4];
    const float* p1v  = (const float*)d_in[5];
    const float* p2w  = (const float*)d_in[6];
    const float* p2g  = (const float*)d_in[7];
    const float* p2b  = (const float*)d_in[8];
    const float* p2m  = (const float*)d_in[9];
    const float* p2v  = (const float*)d_in[10];
    const float* pw   = (const float*)d_in[11];
    const float* pg   = (const float*)d_in[12];
    const float* pb   = (const float*)d_in[13];
    const float* pm   = (const float*)d_in[14];
    const float* pv   = (const float*)d_in[15];
    const float* c1w  = (const float*)d_in[16];
    const float* c1g  = (const float*)d_in[17];
    const float* c1b  = (const float*)d_in[18];
    const float* c1m  = (const float*)d_in[19];
    const float* c1v  = (const float*)d_in[20];
    const float* c2w  = (const float*)d_in[21];
    const float* c2g  = (const float*)d_in[22];
    const float* c2b  = (const float*)d_in[23];
    const float* c2m  = (const float*)d_in[24];
    const float* c2v  = (const float*)d_in[25];

    float* colmax;  cudaGetSymbolAddress((void**)&colmax, g_colmax);
    float* rowmax;  cudaGetSymbolAddress((void**)&rowmax, g_rowmax);
    float* rbuf;    cudaGetSymbolAddress((void**)&rbuf, g_r);

    dim3 blk(16, 8);

    init_max_kernel<<<256, 256>>>();

    conv3_kernel<<<dim3(32, MIDC / 8, BATCH), blk>>>(
        x, p1w, p1g, p1b, p1m, p1v, DIMC, MIDC, 0, colmax);

    conv3_kernel<<<dim3(32, MIDC / 8, BATCH), blk>>>(
        x, p2w, p2g, p2b, p2m, p2v, DIMC, MIDC, 1, rowmax);

    merge_kernel<<<dim3(32, DIMC / 8, BATCH), blk>>>(
        x, pw, pg, pb, pm, pv, c1w, c1g, c1b, c1m, c1v);

    conv3_kernel<<<dim3(32, DIMC / 8, BATCH), blk>>>(
        rbuf, c2w, c2g, c2b, c2m, c2v, DIMC, DIMC, 2, (float*)d_out);
}

// round 9
// speedup vs baseline: 1.5360x; 1.5360x over previous
#include <cuda_runtime.h>
#include <cstdint>

#define BATCH 4
#define DIMC 256
#define MIDC 128
#define HH 128
#define WW 128
#define HW (HH * WW)
#define EPSV 1e-5f

typedef unsigned long long u64;

__device__ __forceinline__ u64 pack2(float lo, float hi) {
    u64 r;
    asm("mov.b64 %0, {%1, %2};" : "=l"(r) : "f"(lo), "f"(hi));
    return r;
}
__device__ __forceinline__ void unpack2(u64 v, float& lo, float& hi) {
    asm("mov.b64 {%0, %1}, %2;" : "=f"(lo), "=f"(hi) : "l"(v));
}
__device__ __forceinline__ void fma2(u64& d, u64 a, u64 b) {
    asm("fma.rn.f32x2 %0, %1, %2, %0;" : "+l"(d) : "l"(a), "l"(b));
}
__device__ __forceinline__ uint32_t smem_u32(const void* p) {
    return (uint32_t)__cvta_generic_to_shared(p);
}
__device__ __forceinline__ void cp4(uint32_t d, const void* s, bool valid) {
    int sz = valid ? 4 : 0;
    asm volatile("cp.async.ca.shared.global [%0], [%1], 4, %2;" :: "r"(d), "l"(s), "r"(sz));
}
__device__ __forceinline__ void cp16(uint32_t d, const void* s) {
    asm volatile("cp.async.cg.shared.global [%0], [%1], 16;" :: "r"(d), "l"(s));
}
__device__ __forceinline__ void cp_commit() { asm volatile("cp.async.commit_group;"); }
__device__ __forceinline__ void cp_wait0() { asm volatile("cp.async.wait_group 0;"); }

__device__ float g_colmax[BATCH * MIDC * WW];
__device__ float g_rowmax[BATCH * MIDC * HH];
__device__ float g_r[(size_t)BATCH * DIMC * HH * WW];

__global__ void init_max_kernel() {
    int i = blockIdx.x * blockDim.x + threadIdx.x;
    if (i < BATCH * MIDC * WW) {
        g_colmax[i] = 0.f;
        g_rowmax[i] = 0.f;
    }
}

// 3x3 conv (pad=1) + BN + ReLU. Tile 16h x 64w, CO=8.
// Thread (xx,yy): out rows (yy, yy+8); pixel pairs (xx,xx+32) & (xx+16,xx+48).
// Interleaved z[s] = (col i, col i+32) filled DIRECTLY by cp.async 4B ops.
__global__ __launch_bounds__(128, 4)
void conv3_kernel(const float* __restrict__ in, const float* __restrict__ wgt,
                  const float* __restrict__ gamma, const float* __restrict__ beta,
                  const float* __restrict__ mean, const float* __restrict__ var,
                  int CIN, int COUT, int mode, float* __restrict__ out)
{
    __shared__ __align__(16) u64 sZ[2][4][18][34];   // interleaved input tile
    __shared__ float sWraw[2][288];
    __shared__ __align__(16) u64 sW[4][3][3][8];     // [ci][dy][dx][co] dup-u64
    __shared__ float sSc[8], sSh[8];
    __shared__ int sMax[8][64];

    const int wt = blockIdx.x & 1, ht = blockIdx.x >> 1;
    const int w0 = wt * 64, h0 = ht * 16;
    const int co0 = blockIdx.y * 8;
    const int b = blockIdx.z;
    const int xx = threadIdx.x, yy = threadIdx.y;
    const int tid = yy * 16 + xx;

    if (tid < 8) {
        int c = co0 + tid;
        float sc = gamma[c] * rsqrtf(var[c] + EPSV);
        sSc[tid] = sc;
        sSh[tid] = beta[c] - mean[c] * sc;
    }
    for (int i = tid; i < 512; i += 128) ((int*)sMax)[i] = 0;

    const float* inb = in + (size_t)b * CIN * HW;
    const int nch = CIN / 4;

    auto stage = [&](int buf, int ci0) {
        uint32_t zb = smem_u32(&sZ[buf][0][0][0]);
        for (int s = tid; s < 2448; s += 128) {
            int ci = s / 612, r = s - ci * 612;
            int hh = r / 34, i = r - hh * 34;
            int gh = h0 - 1 + hh;
            bool vr = (unsigned)gh < (unsigned)HH;
            const float* gp = inb + (size_t)(ci0 + ci) * HW + (vr ? gh : 0) * WW;
            int gw0 = w0 - 1 + i, gw1 = gw0 + 32;
            bool v0 = vr && ((unsigned)gw0 < (unsigned)WW);
            bool v1 = vr && ((unsigned)gw1 < (unsigned)WW);
            uint32_t dst = zb + s * 8;
            cp4(dst, gp + (v0 ? gw0 : 0), v0);
            cp4(dst + 4, gp + (v1 ? gw1 : 0), v1);
        }
        if (tid < 72) {
            int co = tid / 9, q = tid - co * 9;
            cp16(smem_u32(&sWraw[buf][co * 36 + q * 4]),
                 wgt + ((size_t)(co0 + co) * CIN + ci0) * 9 + q * 4);
        }
    };

    stage(0, 0);
    cp_commit();

    u64 acc0[8][2], acc1[8][2];
#pragma unroll
    for (int co = 0; co < 8; co++) {
        acc0[co][0] = 0ULL; acc0[co][1] = 0ULL;
        acc1[co][0] = 0ULL; acc1[co][1] = 0ULL;
    }

    for (int ch = 0; ch < nch; ch++) {
        int buf = ch & 1;
        cp_wait0();
        __syncthreads();
        if (ch + 1 < nch) { stage(buf ^ 1, (ch + 1) * 4); cp_commit(); }

        // expand weights: sW[ci][dy][dx][co] = dup(raw * bn_scale)
        for (int idx = tid; idx < 288; idx += 128) {
            int co = idx / 36, r = idx - co * 36, ci = r / 9, k = r - ci * 9;
            float w = sWraw[buf][idx] * sSc[co];
            sW[ci][k / 3][k % 3][co] = pack2(w, w);
        }
        __syncthreads();

        for (int ci = 0; ci < 4; ci++) {
#pragma unroll
            for (int dy = 0; dy < 3; dy++) {
                const u64* zr0 = &sZ[buf][ci][yy + dy][0];
                const u64* zr1 = &sZ[buf][ci][yy + 8 + dy][0];
                u64 a0 = zr0[xx], a1 = zr0[xx + 1], a2 = zr0[xx + 2];
                u64 b0 = zr0[xx + 16], b1 = zr0[xx + 17], b2 = zr0[xx + 18];
                u64 c0 = zr1[xx], c1 = zr1[xx + 1], c2 = zr1[xx + 2];
                u64 d0 = zr1[xx + 16], d1 = zr1[xx + 17], d2 = zr1[xx + 18];
#pragma unroll
                for (int co = 0; co < 8; co += 2) {
                    ulonglong2 w0v = *(const ulonglong2*)&sW[ci][dy][0][co];
                    ulonglong2 w1v = *(const ulonglong2*)&sW[ci][dy][1][co];
                    ulonglong2 w2v = *(const ulonglong2*)&sW[ci][dy][2][co];
                    fma2(acc0[co][0], w0v.x, a0);     fma2(acc0[co][1], w0v.x, b0);
                    fma2(acc1[co][0], w0v.x, c0);     fma2(acc1[co][1], w0v.x, d0);
                    fma2(acc0[co + 1][0], w0v.y, a0); fma2(acc0[co + 1][1], w0v.y, b0);
                    fma2(acc1[co + 1][0], w0v.y, c0); fma2(acc1[co + 1][1], w0v.y, d0);
                    fma2(acc0[co][0], w1v.x, a1);     fma2(acc0[co][1], w1v.x, b1);
                    fma2(acc1[co][0], w1v.x, c1);     fma2(acc1[co][1], w1v.x, d1);
                    fma2(acc0[co + 1][0], w1v.y, a1); fma2(acc0[co + 1][1], w1v.y, b1);
                    fma2(acc1[co + 1][0], w1v.y, c1); fma2(acc1[co + 1][1], w1v.y, d1);
                    fma2(acc0[co][0], w2v.x, a2);     fma2(acc0[co][1], w2v.x, b2);
                    fma2(acc1[co][0], w2v.x, c2);     fma2(acc1[co][1], w2v.x, d2);
                    fma2(acc0[co + 1][0], w2v.y, a2); fma2(acc0[co + 1][1], w2v.y, b2);
                    fma2(acc1[co + 1][0], w2v.y, c2); fma2(acc1[co + 1][1], w2v.y, d2);
                }
            }
        }
    }

    // acc*[co][0] = cols (w0+xx, w0+xx+32); acc*[co][1] = (w0+xx+16, w0+xx+48)
    if (mode == 2) {
#pragma unroll
        for (int co = 0; co < 8; co++) {
            float v0, v1, v2, v3, u0, u1, u2, u3;
            unpack2(acc0[co][0], v0, v2); unpack2(acc0[co][1], v1, v3);
            unpack2(acc1[co][0], u0, u2); unpack2(acc1[co][1], u1, u3);
            float sh = sSh[co];
            float* op0 = &out[((size_t)(b * COUT + co0 + co) * HH + h0 + yy) * WW + w0];
            float* op1 = op0 + 8 * WW;
            op0[xx] = fmaxf(v0 + sh, 0.f); op0[xx + 16] = fmaxf(v1 + sh, 0.f);
            op0[xx + 32] = fmaxf(v2 + sh, 0.f); op0[xx + 48] = fmaxf(v3 + sh, 0.f);
            op1[xx] = fmaxf(u0 + sh, 0.f); op1[xx + 16] = fmaxf(u1 + sh, 0.f);
            op1[xx + 32] = fmaxf(u2 + sh, 0.f); op1[xx + 48] = fmaxf(u3 + sh, 0.f);
        }
    } else if (mode == 0) {
#pragma unroll
        for (int co = 0; co < 8; co++) {
            float v0, v1, v2, v3, u0, u1, u2, u3;
            unpack2(acc0[co][0], v0, v2); unpack2(acc0[co][1], v1, v3);
            unpack2(acc1[co][0], u0, u2); unpack2(acc1[co][1], u1, u3);
            float sh = sSh[co];
            atomicMax(&sMax[co][xx],      __float_as_int(fmaxf(fmaxf(v0, u0) + sh, 0.f)));
            atomicMax(&sMax[co][xx + 16], __float_as_int(fmaxf(fmaxf(v1, u1) + sh, 0.f)));
            atomicMax(&sMax[co][xx + 32], __float_as_int(fmaxf(fmaxf(v2, u2) + sh, 0.f)));
            atomicMax(&sMax[co][xx + 48], __float_as_int(fmaxf(fmaxf(v3, u3) + sh, 0.f)));
        }
        __syncthreads();
        int* gout = (int*)out;
        for (int i = tid; i < 512; i += 128) {
            int co = i >> 6, w = i & 63;
            atomicMax(&gout[(b * MIDC + co0 + co) * WW + w0 + w], sMax[co][w]);
        }
    } else {
#pragma unroll
        for (int co = 0; co < 8; co++) {
            float v0, v1, v2, v3, u0, u1, u2, u3;
            unpack2(acc0[co][0], v0, v2); unpack2(acc0[co][1], v1, v3);
            unpack2(acc1[co][0], u0, u2); unpack2(acc1[co][1], u1, u3);
            float sh = sSh[co];
            float m0 = fmaxf(fmaxf(v0, v1), fmaxf(v2, v3));
            float m1 = fmaxf(fmaxf(u0, u1), fmaxf(u2, u3));
            atomicMax(&sMax[co][yy],     __float_as_int(fmaxf(m0 + sh, 0.f)));
            atomicMax(&sMax[co][yy + 8], __float_as_int(fmaxf(m1 + sh, 0.f)));
        }
        __syncthreads();
        int* gout = (int*)out;
        if (tid < 128) {
            int co = tid >> 4, h = tid & 15;
            atomicMax(&gout[(b * MIDC + co0 + co) * HH + h0 + h], sMax[co][h]);
        }
    }
}

// Fused merge: r = relu( bn_p(conv3x3(s)) + bn_c1(conv1x1(x)) ),
// s[b,c,h,w] = colmax[b,c,w] + rowmax[b,c,h] (0 outside bounds).
__global__ __launch_bounds__(128, 4)
void merge_kernel(const float* __restrict__ x,
                  const float* __restrict__ pw, const float* __restrict__ pg,
                  const float* __restrict__ pb, const float* __restrict__ pm,
                  const float* __restrict__ pv,
                  const float* __restrict__ c1w, const float* __restrict__ c1g,
                  const float* __restrict__ c1b, const float* __restrict__ c1m,
                  const float* __restrict__ c1v)
{
    __shared__ __align__(16) char sU[32768];   // union: xa (A) / zB (B)
    __shared__ float cmS[2][4][68];
    __shared__ float rmS[2][4][20];
    __shared__ float wrawA[2][32];
    __shared__ __align__(16) u64 sW1[4][8];
    __shared__ float wrawB[2][288];
    __shared__ __align__(16) u64 sWB[4][3][3][8];
    __shared__ float sScP[8], sScC[8], sSh[8];

    float (*xa)[4][16][64] = (float (*)[4][16][64])sU;   // 2 bufs, 32768 B
    u64 (*zB)[18][34]      = (u64 (*)[18][34])sU;        // 19584 B

    const int wt = blockIdx.x & 1, ht = blockIdx.x >> 1;
    const int w0 = wt * 64, h0 = ht * 16;
    const int co0 = blockIdx.y * 8;
    const int b = blockIdx.z;
    const int xx = threadIdx.x, yy = threadIdx.y;
    const int tid = yy * 16 + xx;

    if (tid < 8) {
        int c = co0 + tid;
        float scp = pg[c] * rsqrtf(pv[c] + EPSV);
        float scc = c1g[c] * rsqrtf(c1v[c] + EPSV);
        sScP[tid] = scp;
        sScC[tid] = scc;
        sSh[tid] = (pb[c] - pm[c] * scp) + (c1b[c] - c1m[c] * scc);
    }

    u64 acc0[8][2], acc1[8][2];
#pragma unroll
    for (int co = 0; co < 8; co++) {
        acc0[co][0] = 0ULL; acc0[co][1] = 0ULL;
        acc1[co][0] = 0ULL; acc1[co][1] = 0ULL;
    }

    // ---- Phase A: 1x1 conv over x (raw tile, pack in regs: 4 packs/ci) ----
    const float* xb = x + (size_t)b * DIMC * HW;
    auto stageA = [&](int buf, int ci0) {
        for (int s = tid; s < 1024; s += 128) {
            int ci = s >> 8, r = s & 255;
            int hh = r >> 4, q = r & 15;
            cp16(smem_u32(&xa[buf][ci][hh][q * 4]),
                 xb + (size_t)(ci0 + ci) * HW + (h0 + hh) * WW + w0 + q * 4);
        }
        if (tid < 8)
            cp16(smem_u32(&wrawA[buf][tid * 4]),
                 c1w + (size_t)(co0 + tid) * DIMC + ci0);
    };

    stageA(0, 0);
    cp_commit();
    for (int ch = 0; ch < DIMC / 4; ch++) {
        int buf = ch & 1;
        cp_wait0();
        __syncthreads();
        if (ch + 1 < DIMC / 4) { stageA(buf ^ 1, (ch + 1) * 4); cp_commit(); }
        if (tid < 32) {
            int co = tid >> 2, ci = tid & 3;
            float w = wrawA[buf][co * 4 + ci] * sScC[co];
            sW1[ci][co] = pack2(w, w);
        }
        __syncthreads();
        for (int ci = 0; ci < 4; ci++) {
            const float* r0p = &xa[buf][ci][yy][0];
            const float* r1p = &xa[buf][ci][yy + 8][0];
            u64 a = pack2(r0p[xx], r0p[xx + 32]);
            u64 bq = pack2(r0p[xx + 16], r0p[xx + 48]);
            u64 c = pack2(r1p[xx], r1p[xx + 32]);
            u64 d = pack2(r1p[xx + 16], r1p[xx + 48]);
#pragma unroll
            for (int co = 0; co < 8; co += 2) {
                ulonglong2 wv = *(const ulonglong2*)&sW1[ci][co];
                fma2(acc0[co][0], wv.x, a);     fma2(acc0[co][1], wv.x, bq);
                fma2(acc1[co][0], wv.x, c);     fma2(acc1[co][1], wv.x, d);
                fma2(acc0[co + 1][0], wv.y, a); fma2(acc0[co + 1][1], wv.y, bq);
                fma2(acc1[co + 1][0], wv.y, c); fma2(acc1[co + 1][1], wv.y, d);
            }
        }
    }
    cp_wait0();
    __syncthreads();   // drain before union region switches to zB

    // ---- Phase B: 3x3 conv over s ----
    auto stageB = [&](int buf, int ci0) {
        for (int s = tid; s < 264; s += 128) {
            int ci = s / 66, i = s - ci * 66;
            int gw = w0 - 1 + i;
            bool v = (unsigned)gw < (unsigned)WW;
            cp4(smem_u32(&cmS[buf][ci][i]),
                g_colmax + (b * MIDC + ci0 + ci) * WW + (v ? gw : 0), v);
        }
        if (tid < 72) {
            int ci = tid / 18, hh = tid - ci * 18;
            int gh = h0 - 1 + hh;
            bool v = (unsigned)gh < (unsigned)HH;
            cp4(smem_u32(&rmS[buf][ci][hh]),
                g_rowmax + (b * MIDC + ci0 + ci) * HH + (v ? gh : 0), v);
        }
        if (tid < 72) {
            int co = tid / 9, q = tid - co * 9;
            cp16(smem_u32(&wrawB[buf][co * 36 + q * 4]),
                 pw + ((size_t)(co0 + co) * MIDC + ci0) * 9 + q * 4);
        }
    };

    stageB(0, 0);
    cp_commit();
    for (int ch = 0; ch < MIDC / 4; ch++) {
        int buf = ch & 1;
        cp_wait0();
        __syncthreads();
        if (ch + 1 < MIDC / 4) { stageB(buf ^ 1, (ch + 1) * 4); cp_commit(); }

        for (int idx = tid; idx < 288; idx += 128) {
            int co = idx / 36, r = idx - co * 36, ci = r / 9, k = r - ci * 9;
            float w = wrawB[buf][idx] * sScP[co];
            sWB[ci][k / 3][k % 3][co] = pack2(w, w);
        }
        // build interleaved s tile (single-buffered zB)
        for (int s = tid; s < 2448; s += 128) {
            int ci = s / 612, r = s - ci * 612;
            int hh = r / 34, i = r - hh * 34;
            bool vh = (unsigned)(h0 - 1 + hh) < (unsigned)HH;
            bool vw0 = (unsigned)(w0 - 1 + i) < (unsigned)WW;
            bool vw1 = (unsigned)(w0 + 31 + i) < (unsigned)WW;
            float rmv = rmS[buf][ci][hh];
            float lo = (vh && vw0) ? (cmS[buf][ci][i] + rmv) : 0.f;
            float hi = (vh && vw1) ? (cmS[buf][ci][i + 32] + rmv) : 0.f;
            ((u64*)zB)[s] = pack2(lo, hi);
        }
        __syncthreads();

        for (int ci = 0; ci < 4; ci++) {
#pragma unroll
            for (int dy = 0; dy < 3; dy++) {
                const u64* zr0 = &zB[ci][yy + dy][0];
                const u64* zr1 = &zB[ci][yy + 8 + dy][0];
                u64 a0 = zr0[xx], a1 = zr0[xx + 1], a2 = zr0[xx + 2];
                u64 b0 = zr0[xx + 16], b1 = zr0[xx + 17], b2 = zr0[xx + 18];
                u64 c0 = zr1[xx], c1 = zr1[xx + 1], c2 = zr1[xx + 2];
                u64 d0 = zr1[xx + 16], d1 = zr1[xx + 17], d2 = zr1[xx + 18];
#pragma unroll
                for (int co = 0; co < 8; co += 2) {
                    ulonglong2 w0v = *(const ulonglong2*)&sWB[ci][dy][0][co];
                    ulonglong2 w1v = *(const ulonglong2*)&sWB[ci][dy][1][co];
                    ulonglong2 w2v = *(const ulonglong2*)&sWB[ci][dy][2][co];
                    fma2(acc0[co][0], w0v.x, a0);     fma2(acc0[co][1], w0v.x, b0);
                    fma2(acc1[co][0], w0v.x, c0);     fma2(acc1[co][1], w0v.x, d0);
                    fma2(acc0[co + 1][0], w0v.y, a0); fma2(acc0[co + 1][1], w0v.y, b0);
                    fma2(acc1[co + 1][0], w0v.y, c0); fma2(acc1[co + 1][1], w0v.y, d0);
                    fma2(acc0[co][0], w1v.x, a1);     fma2(acc0[co][1], w1v.x, b1);
                    fma2(acc1[co][0], w1v.x, c1);     fma2(acc1[co][1], w1v.x, d1);
                    fma2(acc0[co + 1][0], w1v.y, a1); fma2(acc0[co + 1][1], w1v.y, b1);
                    fma2(acc1[co + 1][0], w1v.y, c1); fma2(acc1[co + 1][1], w1v.y, d1);
                    fma2(acc0[co][0], w2v.x, a2);     fma2(acc0[co][1], w2v.x, b2);
                    fma2(acc1[co][0], w2v.x, c2);     fma2(acc1[co][1], w2v.x, d2);
                    fma2(acc0[co + 1][0], w2v.y, a2); fma2(acc0[co + 1][1], w2v.y, b2);
                    fma2(acc1[co + 1][0], w2v.y, c2); fma2(acc1[co + 1][1], w2v.y, d2);
                }
            }
        }
        __syncthreads();   // zB reused next chunk
    }

    // epilogue
#pragma unroll
    for (int co = 0; co < 8; co++) {
        float v0, v1, v2, v3, u0, u1, u2, u3;
        unpack2(acc0[co][0], v0, v2); unpack2(acc0[co][1], v1, v3);
        unpack2(acc1[co][0], u0, u2); unpack2(acc1[co][1], u1, u3);
        float sh = sSh[co];
        float* op0 = &g_r[((size_t)(b * DIMC + co0 + co) * HH + h0 + yy) * WW + w0];
        float* op1 = op0 + 8 * WW;
        op0[xx] = fmaxf(v0 + sh, 0.f); op0[xx + 16] = fmaxf(v1 + sh, 0.f);
        op0[xx + 32] = fmaxf(v2 + sh, 0.f); op0[xx + 48] = fmaxf(v3 + sh, 0.f);
        op1[xx] = fmaxf(u0 + sh, 0.f); op1[xx + 16] = fmaxf(u1 + sh, 0.f);
        op1[xx + 32] = fmaxf(u2 + sh, 0.f); op1[xx + 48] = fmaxf(u3 + sh, 0.f);
    }
}

extern "C" void kernel_launch(void* const* d_in, const int* in_sizes, int n_in,
                              void* d_out, int out_size)
{
    const float* x    = (const float*)d_in[0];
    const float* p1w  = (const float*)d_in[1];
    const float* p1g  = (const float*)d_in[2];
    const float* p1b  = (const float*)d_in[3];
    const float* p1m  = (const float*)d_in[4];
    const float* p1v  = (const float*)d_in[5];
    const float* p2w  = (const float*)d_in[6];
    const float* p2g  = (const float*)d_in[7];
    const float* p2b  = (const float*)d_in[8];
    const float* p2m  = (const float*)d_in[9];
    const float* p2v  = (const float*)d_in[10];
    const float* pw   = (const float*)d_in[11];
    const float* pg   = (const float*)d_in[12];
    const float* pb   = (const float*)d_in[13];
    const float* pm   = (const float*)d_in[14];
    const float* pv   = (const float*)d_in[15];
    const float* c1w  = (const float*)d_in[16];
    const float* c1g  = (const float*)d_in[17];
    const float* c1b  = (const float*)d_in[18];
    const float* c1m  = (const float*)d_in[19];
    const float* c1v  = (const float*)d_in[20];
    const float* c2w  = (const float*)d_in[21];
    const float* c2g  = (const float*)d_in[22];
    const float* c2b  = (const float*)d_in[23];
    const float* c2m  = (const float*)d_in[24];
    const float* c2v  = (const float*)d_in[25];

    float* colmax;  cudaGetSymbolAddress((void**)&colmax, g_colmax);
    float* rowmax;  cudaGetSymbolAddress((void**)&rowmax, g_rowmax);
    float* rbuf;    cudaGetSymbolAddress((void**)&rbuf, g_r);

    dim3 blk(16, 8);

    init_max_kernel<<<256, 256>>>();

    conv3_kernel<<<dim3(16, MIDC / 8, BATCH), blk>>>(
        x, p1w, p1g, p1b, p1m, p1v, DIMC, MIDC, 0, colmax);

    conv3_kernel<<<dim3(16, MIDC / 8, BATCH), blk>>>(
        x, p2w, p2g, p2b, p2m, p2v, DIMC, MIDC, 1, rowmax);

    merge_kernel<<<dim3(16, DIMC / 8, BATCH), blk>>>(
        x, pw, pg, pb, pm, pv, c1w, c1g, c1b, c1m, c1v);

    conv3_kernel<<<dim3(16, DIMC / 8, BATCH), blk>>>(
        rbuf, c2w, c2g, c2b, c2m, c2v, DIMC, DIMC, 2, (float*)d_out);
}